// round 5
// baseline (speedup 1.0000x reference)
#include <cuda_runtime.h>
#include <math.h>

// out[row] = tanh(sqrt(sum_j (w[row][j] - x[j])^2)), row 0..1048575, j 0..255
// Persistent warps, grid-stride over row-PAIRS (2 rows = 4 coalesced 512B loads
// per iteration), with one-iteration software prefetch so the DRAM pipe is fed
// continuously instead of in one-shot bursts. Single logical wave -> no wave
// transitions, steady L1tex queue pressure.

__global__ __launch_bounds__(256, 4) void sonia_l2_tanh_persist(
    const float* __restrict__ x,
    const float* __restrict__ w,
    float* __restrict__ out,
    int n_pairs)                       // n_rows / 2
{
    const int gwarp  = (blockIdx.x * blockDim.x + threadIdx.x) >> 5;
    const int nwarps = (gridDim.x * blockDim.x) >> 5;
    const int lane   = threadIdx.x & 31;

    const float4* __restrict__ xr = reinterpret_cast<const float4*>(x);
    const float4 x0 = __ldg(xr + lane);
    const float4 x1 = __ldg(xr + lane + 32);

    int pair = gwarp;
    if (pair >= n_pairs) return;

    // Prologue: prefetch first iteration (2 rows = 4x float4 per lane).
    const float4* __restrict__ wp = reinterpret_cast<const float4*>(w) + (size_t)pair * 128;
    float4 a0 = __ldcs(wp + lane);
    float4 a1 = __ldcs(wp + lane + 32);
    float4 b0 = __ldcs(wp + lane + 64);
    float4 b1 = __ldcs(wp + lane + 96);

    while (true) {
        const int next = pair + nwarps;

        // Prefetch next iteration before consuming current: these 4 loads sit
        // in flight behind the scoreboard while we do ~30 FMA + 10 SHFL below.
        float4 na0, na1, nb0, nb1;
        const bool have_next = (next < n_pairs);
        if (have_next) {
            const float4* __restrict__ wn =
                reinterpret_cast<const float4*>(w) + (size_t)next * 128;
            na0 = __ldcs(wn + lane);
            na1 = __ldcs(wn + lane + 32);
            nb0 = __ldcs(wn + lane + 64);
            nb1 = __ldcs(wn + lane + 96);
        }

        float d, sa = 0.0f, sb = 0.0f;
        d = a0.x - x0.x; sa = fmaf(d, d, sa);
        d = a0.y - x0.y; sa = fmaf(d, d, sa);
        d = a0.z - x0.z; sa = fmaf(d, d, sa);
        d = a0.w - x0.w; sa = fmaf(d, d, sa);
        d = a1.x - x1.x; sa = fmaf(d, d, sa);
        d = a1.y - x1.y; sa = fmaf(d, d, sa);
        d = a1.z - x1.z; sa = fmaf(d, d, sa);
        d = a1.w - x1.w; sa = fmaf(d, d, sa);

        d = b0.x - x0.x; sb = fmaf(d, d, sb);
        d = b0.y - x0.y; sb = fmaf(d, d, sb);
        d = b0.z - x0.z; sb = fmaf(d, d, sb);
        d = b0.w - x0.w; sb = fmaf(d, d, sb);
        d = b1.x - x1.x; sb = fmaf(d, d, sb);
        d = b1.y - x1.y; sb = fmaf(d, d, sb);
        d = b1.z - x1.z; sb = fmaf(d, d, sb);
        d = b1.w - x1.w; sb = fmaf(d, d, sb);

        #pragma unroll
        for (int off = 16; off > 0; off >>= 1) {
            sa += __shfl_xor_sync(0xFFFFFFFFu, sa, off);
            sb += __shfl_xor_sync(0xFFFFFFFFu, sb, off);
        }

        if (lane == 0) {
            const int row0 = pair * 2;
            out[row0]     = tanhf(sqrtf(sa));
            out[row0 + 1] = tanhf(sqrtf(sb));
        }

        if (!have_next) break;
        a0 = na0; a1 = na1; b0 = nb0; b1 = nb1;
        pair = next;
    }
}

extern "C" void kernel_launch(void* const* d_in, const int* in_sizes, int n_in,
                              void* d_out, int out_size)
{
    const float* x = (const float*)d_in[0];   // input  [1, 256]
    const float* w = (const float*)d_in[1];   // weight [out_size, 256]
    float* out     = (float*)d_out;

    const int n_rows  = out_size;             // 1048576 (even)
    const int n_pairs = n_rows >> 1;          // 524288

    // Persistent-ish grid: 148 SMs x 4 CTAs (launch_bounds occupancy target)
    // = 592 resident CTAs; launch exactly that -> one logical wave, each warp
    // iterates ~110 times with continuous prefetch.
    const int blocks = 148 * 4;

    sonia_l2_tanh_persist<<<blocks, 256>>>(x, w, out, n_pairs);
}

// round 6
// speedup vs baseline: 1.0374x; 1.0374x over previous
#include <cuda_runtime.h>
#include <math.h>

// out[row] = tanh(sqrt(sum_j (w[row][j] - x[j])^2)), row in [0, 1048576), j in [0, 256)
// R2 winner structure (2 rows/warp, 4 front-batched coalesced 512B streaming
// loads, 32-reg friendly) with block=512 for fewer CTAs / better ramp.

__global__ __launch_bounds__(512, 4) void sonia_l2_tanh_kernel2w(
    const float* __restrict__ x,
    const float* __restrict__ w,
    float* __restrict__ out,
    int n_rows)
{
    const int warp_id = (blockIdx.x * blockDim.x + threadIdx.x) >> 5;
    const int lane    = threadIdx.x & 31;
    const int row0    = warp_id * 2;
    if (row0 >= n_rows) return;

    const float4* __restrict__ wr = reinterpret_cast<const float4*>(w) + (size_t)row0 * 64;
    const float4* __restrict__ xr = reinterpret_cast<const float4*>(x);

    // x is tiny and re-read by every warp: L1/L2 resident.
    const float4 x0 = __ldg(xr + lane);
    const float4 x1 = __ldg(xr + lane + 32);

    // 4 independent streaming loads (evict-first: pure pass-through data).
    const float4 a0 = __ldcs(wr + lane);
    const float4 a1 = __ldcs(wr + lane + 32);
    const float4 b0 = __ldcs(wr + lane + 64);
    const float4 b1 = __ldcs(wr + lane + 96);

    float d;
    float sa = 0.0f, sb = 0.0f;
    d = a0.x - x0.x; sa = fmaf(d, d, sa);
    d = a0.y - x0.y; sa = fmaf(d, d, sa);
    d = a0.z - x0.z; sa = fmaf(d, d, sa);
    d = a0.w - x0.w; sa = fmaf(d, d, sa);
    d = a1.x - x1.x; sa = fmaf(d, d, sa);
    d = a1.y - x1.y; sa = fmaf(d, d, sa);
    d = a1.z - x1.z; sa = fmaf(d, d, sa);
    d = a1.w - x1.w; sa = fmaf(d, d, sa);

    d = b0.x - x0.x; sb = fmaf(d, d, sb);
    d = b0.y - x0.y; sb = fmaf(d, d, sb);
    d = b0.z - x0.z; sb = fmaf(d, d, sb);
    d = b0.w - x0.w; sb = fmaf(d, d, sb);
    d = b1.x - x1.x; sb = fmaf(d, d, sb);
    d = b1.y - x1.y; sb = fmaf(d, d, sb);
    d = b1.z - x1.z; sb = fmaf(d, d, sb);
    d = b1.w - x1.w; sb = fmaf(d, d, sb);

    // Butterfly reduce both sums across the warp.
    #pragma unroll
    for (int off = 16; off > 0; off >>= 1) {
        sa += __shfl_xor_sync(0xFFFFFFFFu, sa, off);
        sb += __shfl_xor_sync(0xFFFFFFFFu, sb, off);
    }

    if (lane == 0) {
        out[row0] = tanhf(sqrtf(sa));
        if (row0 + 1 < n_rows)
            out[row0 + 1] = tanhf(sqrtf(sb));
    }
}

extern "C" void kernel_launch(void* const* d_in, const int* in_sizes, int n_in,
                              void* d_out, int out_size)
{
    const float* x = (const float*)d_in[0];   // input  [1, 256]
    const float* w = (const float*)d_in[1];   // weight [out_size, 256]
    float* out     = (float*)d_out;

    const int n_rows = out_size;              // 1048576
    // 16 warps/block, 2 rows/warp -> 32 rows per block
    const int rows_per_block = 32;
    const int blocks = (n_rows + rows_per_block - 1) / rows_per_block;

    sonia_l2_tanh_kernel2w<<<blocks, 512>>>(x, w, out, n_rows);
}